// round 7
// baseline (speedup 1.0000x reference)
#include <cuda_runtime.h>
#include <cuda_bf16.h>
#include <cstdint>
#include <cstddef>

// ---------------- problem dims ----------------
#define HD    512
#define BATCH 1024
#define TSEQ  512
#define PLEN  96
#define DIN   32

// ---------------- tiling ----------------
#define NCTA 128
#define MT   8          // m-tiles (BATCH/128)
#define NTL  16         // n-tiles (HD/32)
#define BMR  128        // batch rows per CTA
#define BNR  96         // gate rows of W per CTA (3 gates x 32)
#define KC   64         // k per chunk

#define A_ELE (BMR*KC)  // 8192
#define B_ELE (BNR*KC)  // 6144
#define A_BYT (A_ELE*2) // 16384
#define B_BYT (B_ELE*2) // 12288
#define BUF_BYTES (2*A_BYT + 2*B_BYT)   // 57344
#define NSTAGE 3
#define SM_TOTAL  (NSTAGE*BUF_BYTES)    // 172032

// ---------------- device globals (static scratch) ----------------
__device__ float g_h1[2][BATCH*HD];
__device__ float g_h2[2][BATCH*HD];
__device__ __align__(16) __nv_bfloat16 g_h1bf[2][MT][8][2][A_ELE];
__device__ __align__(16) __nv_bfloat16 g_h2bf[2][MT][8][2][A_ELE];
__device__ __align__(16) __nv_bfloat16 g_xbf[TSEQ][MT][A_ELE];     // [xhi|xlo] k64
__device__ __align__(16) __nv_bfloat16 g_w[6][NTL][8][2][B_ELE];   // 0:e0hh 1:e1ih 2:e1hh 3:d0hh 4:d1ih 5:d1hh
__device__ __align__(16) __nv_bfloat16 g_wx[NTL][2][B_ELE];        // enc0 Wih: B1=[Whi|Whi], B2=[Wlo|0]
__device__ float g_br[4][HD], g_bz[4][HD], g_bin[4][HD], g_bhn[4][HD];
__device__ float g_y[BATCH];
__device__ unsigned g_cnt, g_gen;

// ---------------- tile addressing (ldmatrix-friendly swizzle) ----------------
__host__ __device__ __forceinline__ int offel(int r, int k) {
    return r * 64 + ((((k >> 3) ^ (r & 7)) << 3) | (k & 7));
}

// ---------------- PTX helpers ----------------
__device__ __forceinline__ uint32_t smem_u32(const void* p) {
    uint32_t a;
    asm("{ .reg .u64 t; cvta.to.shared.u64 t, %1; cvt.u32.u64 %0, t; }" : "=r"(a) : "l"(p));
    return a;
}
#define LDSM4(r, addr) asm volatile("ldmatrix.sync.aligned.m8n8.x4.shared.b16 {%0,%1,%2,%3},[%4];" \
    : "=r"((r)[0]), "=r"((r)[1]), "=r"((r)[2]), "=r"((r)[3]) : "r"(addr))
#define MMAB(d, a, b0, b1) asm volatile( \
    "mma.sync.aligned.m16n8k16.row.col.f32.bf16.bf16.f32 {%0,%1,%2,%3},{%4,%5,%6,%7},{%8,%9},{%0,%1,%2,%3};" \
    : "+f"((d)[0]), "+f"((d)[1]), "+f"((d)[2]), "+f"((d)[3]) \
    : "r"((a)[0]), "r"((a)[1]), "r"((a)[2]), "r"((a)[3]), "r"(b0), "r"(b1))
#define CPA16(sa, gp) asm volatile("cp.async.cg.shared.global [%0],[%1],16;" :: "r"(sa), "l"(gp))
#define CPCOMMIT()    asm volatile("cp.async.commit_group;" ::: "memory")
#define CPWAIT1()     asm volatile("cp.async.wait_group 1;" ::: "memory")
#define CPWAIT0()     asm volatile("cp.async.wait_group 0;" ::: "memory")

// ---------------- init kernels ----------------
__global__ void init_weights(
    const float* __restrict__ eWih0,
    const float* __restrict__ eWhh0, const float* __restrict__ eWih1, const float* __restrict__ eWhh1,
    const float* __restrict__ dWhh0, const float* __restrict__ dWih1, const float* __restrict__ dWhh1,
    const float* __restrict__ ebih0, const float* __restrict__ ebhh0,
    const float* __restrict__ ebih1, const float* __restrict__ ebhh1,
    const float* __restrict__ dbih0, const float* __restrict__ dbhh0,
    const float* __restrict__ dbih1, const float* __restrict__ dbhh1)
{
    const float* Wsrc[6] = {eWhh0, eWih1, eWhh1, dWhh0, dWih1, dWhh1};
    const long stride = (long)gridDim.x * blockDim.x;
    const long i0 = (long)blockIdx.x * blockDim.x + threadIdx.x;

    const long totW = 6L * NTL * 8 * BNR * KC;
    for (long i = i0; i < totW; i += stride) {
        int k = (int)(i % KC); long q = i / KC;
        int r = (int)(q % BNR); q /= BNR;
        int ch = (int)(q % 8); q /= 8;
        int nt = (int)(q % NTL); int ty = (int)(q / NTL);
        int g = r >> 5, jl = r & 31, j = nt * 32 + jl, kg = ch * KC + k;
        float v = Wsrc[ty][(size_t)(g * HD + j) * HD + kg];
        __nv_bfloat16 hi = __float2bfloat16(v);
        __nv_bfloat16 lo = __float2bfloat16(v - __bfloat162float(hi));
        int oe = offel(r, k);
        g_w[ty][nt][ch][0][oe] = hi;
        g_w[ty][nt][ch][1][oe] = lo;
    }
    // enc0 Wih (K=32): B1 = [Whi | Whi], B2 = [Wlo | 0]
    const long totX = (long)NTL * BNR * KC;
    for (long i = i0; i < totX; i += stride) {
        int k = (int)(i % KC); long q = i / KC;
        int r = (int)(q % BNR); int nt = (int)(q / BNR);
        int g = r >> 5, jl = r & 31, j = nt * 32 + jl, kk = k & 31;
        float v = eWih0[(size_t)(g * HD + j) * DIN + kk];
        __nv_bfloat16 hi = __float2bfloat16(v);
        __nv_bfloat16 lo = __float2bfloat16(v - __bfloat162float(hi));
        int oe = offel(r, k);
        g_wx[nt][0][oe] = hi;
        g_wx[nt][1][oe] = (k < 32) ? lo : __float2bfloat16(0.f);
    }
    const float* bi[4] = {ebih0, ebih1, dbih0, dbih1};
    const float* bh[4] = {ebhh0, ebhh1, dbhh0, dbhh1};
    for (long i = i0; i < 4 * HD; i += stride) {
        int tt = (int)(i / HD), j = (int)(i % HD);
        g_br[tt][j]  = bi[tt][j] + bh[tt][j];
        g_bz[tt][j]  = bi[tt][HD + j] + bh[tt][HD + j];
        g_bin[tt][j] = bi[tt][2 * HD + j];
        g_bhn[tt][j] = bh[tt][2 * HD + j];
    }
}

__global__ void init_x(const float* __restrict__ x)
{
    const long stride = (long)gridDim.x * blockDim.x;
    const long tot = (long)TSEQ * MT * BMR * KC;
    for (long i = (long)blockIdx.x * blockDim.x + threadIdx.x; i < tot; i += stride) {
        int k = (int)(i % KC); long q = i / KC;
        int r = (int)(q % BMR); q /= BMR;
        int mt = (int)(q % MT); int t = (int)(q / MT);
        int b = mt * BMR + r, c = k & 31;
        float v = x[((long)b * TSEQ + t) * DIN + c];
        __nv_bfloat16 hi = __float2bfloat16(v);
        __nv_bfloat16 val = (k < 32) ? hi : __float2bfloat16(v - __bfloat162float(hi));
        g_xbf[t][mt][offel(r, k)] = val;
    }
}

// ---------------- grid barrier ----------------
__device__ __forceinline__ void gbar()
{
    __syncthreads();
    if (threadIdx.x == 0) {
        __threadfence();
        unsigned gen = *(volatile unsigned*)&g_gen;
        unsigned t = atomicAdd(&g_cnt, 1u);
        if (t == NCTA - 1) {
            *(volatile unsigned*)&g_cnt = 0;
            __threadfence();
            *(volatile unsigned*)&g_gen = gen + 1;
        } else {
            while (*(volatile unsigned*)&g_gen == gen) __nanosleep(32);
        }
        __threadfence();
    }
    __syncthreads();
}

// ---------------- chunk compute: 2D warp tiling 4m x 2n ----------------
template<int MODE>
__device__ __forceinline__ void compute_chunk(
    uint32_t sbuf, int lane, int wm, int wn,
    float (&aR)[2][2][4], float (&aZ)[2][2][4],
    float (&aNH)[2][2][4], float (&aNI)[2][2][4])
{
    const uint32_t sA = sbuf, sAlo = sbuf + A_BYT;
    const uint32_t sB = sbuf + 2 * A_BYT, sBlo = sB + B_BYT;
    const int a_row = wm * 32 + (lane & 7) + ((lane >> 3) & 1) * 8;
    const int a_kh  = (lane >> 4) * 8;
    const int b_roff = (lane & 7) + ((lane >> 4) & 1) * 8;
    const int b_kh   = ((lane >> 3) & 1) * 8;

#pragma unroll
    for (int kq = 0; kq < 4; kq++) {
        const int kb = kq * 16;
        uint32_t ahi[2][4], alo[2][4];
#pragma unroll
        for (int mtl = 0; mtl < 2; mtl++) {
            const uint32_t ao = 2u * (uint32_t)offel(a_row + mtl * 16, kb + a_kh);
            LDSM4(ahi[mtl], sA + ao);
            if (MODE != 2) LDSM4(alo[mtl], sAlo + ao);
        }
#pragma unroll
        for (int g = 0; g < 3; g++) {
            const uint32_t bo = 2u * (uint32_t)offel(g * 32 + wn * 16 + b_roff, kb + b_kh);
            uint32_t bhi[4], blo[4];
            LDSM4(bhi, sB + bo);
            LDSM4(blo, sBlo + bo);
#pragma unroll
            for (int mtl = 0; mtl < 2; mtl++) {
#pragma unroll
                for (int n8 = 0; n8 < 2; n8++) {
                    float* dst = (g == 0) ? aR[mtl][n8]
                               : (g == 1) ? aZ[mtl][n8]
                               : (MODE == 0 ? aNH[mtl][n8] : aNI[mtl][n8]);
                    MMAB(dst, ahi[mtl], bhi[2 * n8], bhi[2 * n8 + 1]);
                    if (MODE == 2) {
                        MMAB(dst, ahi[mtl], blo[2 * n8], blo[2 * n8 + 1]);
                    } else {
                        MMAB(dst, alo[mtl], bhi[2 * n8], bhi[2 * n8 + 1]);
                        MMAB(dst, ahi[mtl], blo[2 * n8], blo[2 * n8 + 1]);
                    }
                }
            }
        }
    }
}

struct Ck { const char* A; const char* B; int mode; };

// ---------------- persistent kernel ----------------
__global__ void __launch_bounds__(256, 1) gru_tc(
    const float* __restrict__ dWih0,
    const float* __restrict__ outW, const float* __restrict__ outb,
    const float* __restrict__ dstart, float* __restrict__ out)
{
    extern __shared__ char smem[];
    const int tid = threadIdx.x, wid = tid >> 5, lane = tid & 31;
    const int wm = wid & 3, wn = wid >> 2;
    const int mt = blockIdx.x >> 4, nt = blockIdx.x & 15;

    // ---- per-launch state init ----
    {
        const long gs = (long)NCTA * 256;
        for (long i = (long)blockIdx.x * 256 + tid; i < (long)BATCH * HD; i += gs) {
            g_h1[0][i] = 0.f; g_h2[0][i] = 0.f;
        }
        uint32_t* z1 = (uint32_t*)&g_h1bf[0][0][0][0][0];
        uint32_t* z2 = (uint32_t*)&g_h2bf[0][0][0][0][0];
        const long nz = (long)MT * 8 * 2 * A_ELE / 2;
        for (long i = (long)blockIdx.x * 256 + tid; i < nz; i += gs) { z1[i] = 0; z2[i] = 0; }
        for (long i = (long)blockIdx.x * 256 + tid; i < BATCH; i += gs) g_y[i] = dstart[0];
    }
    gbar();

    float aR[2][2][4], aZ[2][2][4], aNH[2][2][4], aNI[2][2][4];

    auto zero_acc = [&]() {
#pragma unroll
        for (int a = 0; a < 2; a++)
#pragma unroll
            for (int b = 0; b < 2; b++)
#pragma unroll
                for (int c = 0; c < 4; c++) {
                    aR[a][b][c] = 0.f; aZ[a][b][c] = 0.f;
                    aNH[a][b][c] = 0.f; aNI[a][b][c] = 0.f;
                }
    };

    auto load_chunk = [&](int buf, const Ck& c) {
        uint32_t dst = smem_u32(smem) + buf * BUF_BYTES;
        const int nA = (c.mode == 2 ? A_BYT : 2 * A_BYT) >> 4;
        for (int i = tid; i < nA; i += 256) CPA16(dst + i * 16, c.A + i * 16);
        const uint32_t bdst = dst + 2 * A_BYT;
        for (int i = tid; i < (2 * B_BYT) >> 4; i += 256) CPA16(bdst + i * 16, c.B + i * 16);
        CPCOMMIT();
    };

    // 3-stage pipeline: 2 loads in flight under every compute, 1 sync/chunk.
    auto run_seg = [&](const Ck* cks, int n) {
        load_chunk(0, cks[0]);
        if (n > 1) load_chunk(1, cks[1]);
        int buf = 0;
        for (int i = 0; i < n; i++) {
            if (i + 1 < n) CPWAIT1(); else CPWAIT0();
            __syncthreads();           // buffer i ready for all; buffer (i+2)%3 free for all
            if (i + 2 < n) load_chunk((buf + 2) % NSTAGE, cks[i + 2]);
            const uint32_t sbuf = smem_u32(smem) + buf * BUF_BYTES;
            const int m = cks[i].mode;
            if (m == 0)      compute_chunk<0>(sbuf, lane, wm, wn, aR, aZ, aNH, aNI);
            else if (m == 1) compute_chunk<1>(sbuf, lane, wm, wn, aR, aZ, aNH, aNI);
            else             compute_chunk<2>(sbuf, lane, wm, wn, aR, aZ, aNH, aNI);
            buf = (buf + 1) % NSTAGE;
        }
        __syncthreads();               // protect buffers before next segment's prefetch
    };

    // epilogue: gates + state update. dec0W != null => decoder layer0 scalar input.
    auto epilogue = [&](int bt, const float* hprev, float* hout,
                        char* hbfbase, const float* dec0W) {
        const int qr = lane >> 2, qc = lane & 3;
        const int kbase = (nt & 1) * 32;
#pragma unroll
        for (int mtl = 0; mtl < 2; mtl++) {
#pragma unroll
            for (int fr = 0; fr < 2; fr++) {
                const int rloc = wm * 32 + mtl * 16 + qr + fr * 8;
                const int grow = mt * 128 + rloc;
                const float yy = dec0W ? __ldcg(&g_y[grow]) : 0.f;
#pragma unroll
                for (int n8 = 0; n8 < 2; n8++) {
#pragma unroll
                    for (int e = 0; e < 2; e++) {
                        const int jl = wn * 16 + n8 * 8 + qc * 2 + e;
                        const int j = nt * 32 + jl;
                        const int ci = fr * 2 + e;
                        float rv = aR[mtl][n8][ci], zv = aZ[mtl][n8][ci];
                        float nh = aNH[mtl][n8][ci], ni = aNI[mtl][n8][ci];
                        if (dec0W) {
                            rv += yy * dec0W[j];
                            zv += yy * dec0W[HD + j];
                            ni += yy * dec0W[2 * HD + j];
                        }
                        const float r = 1.f / (1.f + __expf(-(rv + g_br[bt][j])));
                        const float z = 1.f / (1.f + __expf(-(zv + g_bz[bt][j])));
                        const float n = tanhf(ni + g_bin[bt][j] + r * (nh + g_bhn[bt][j]));
                        const float hp = hprev[(size_t)grow * HD + j];
                        const float hv = n + z * (hp - n);
                        hout[(size_t)grow * HD + j] = hv;
                        __nv_bfloat16 hi = __float2bfloat16(hv);
                        __nv_bfloat16 lo = __float2bfloat16(hv - __bfloat162float(hi));
                        const int oe = offel(rloc, kbase + jl);
                        ((__nv_bfloat16*)hbfbase)[oe] = hi;
                        ((__nv_bfloat16*)(hbfbase + A_BYT))[oe] = lo;
                    }
                }
            }
        }
    };

    Ck ckA[9], ckB[8];
    int p = 0;

    // ---------------- encoder: 512 steps ----------------
    for (int t = 0; t < TSEQ; t++) {
        for (int c = 0; c < 8; c++)
            ckA[c] = { (const char*)&g_h1bf[p][mt][c][0][0],
                       (const char*)&g_w[0][nt][c][0][0], 0 };
        ckA[8] = { (const char*)&g_xbf[t][mt][0], (const char*)&g_wx[nt][0][0], 2 };
        zero_acc();
        run_seg(ckA, 9);
        epilogue(0, g_h1[p], g_h1[1 - p], (char*)&g_h1bf[1 - p][mt][nt >> 1][0][0], nullptr);
        // layer 1: hidden GEMM first (old h2), gbar, then input GEMM (new h1)
        for (int c = 0; c < 8; c++) {
            ckA[c] = { (const char*)&g_h2bf[p][mt][c][0][0],
                       (const char*)&g_w[2][nt][c][0][0], 0 };
            ckB[c] = { (const char*)&g_h1bf[1 - p][mt][c][0][0],
                       (const char*)&g_w[1][nt][c][0][0], 1 };
        }
        zero_acc();
        run_seg(ckA, 8);
        gbar();
        run_seg(ckB, 8);
        epilogue(1, g_h2[p], g_h2[1 - p], (char*)&g_h2bf[1 - p][mt][nt >> 1][0][0], nullptr);
        gbar();
        p ^= 1;
    }

    // ---------------- decoder: 96 steps ----------------
    for (int s = 0; s < PLEN; s++) {
        for (int c = 0; c < 8; c++)
            ckA[c] = { (const char*)&g_h1bf[p][mt][c][0][0],
                       (const char*)&g_w[3][nt][c][0][0], 0 };
        zero_acc();
        run_seg(ckA, 8);
        epilogue(2, g_h1[p], g_h1[1 - p], (char*)&g_h1bf[1 - p][mt][nt >> 1][0][0], dWih0);
        for (int c = 0; c < 8; c++) {
            ckA[c] = { (const char*)&g_h2bf[p][mt][c][0][0],
                       (const char*)&g_w[5][nt][c][0][0], 0 };
            ckB[c] = { (const char*)&g_h1bf[1 - p][mt][c][0][0],
                       (const char*)&g_w[4][nt][c][0][0], 1 };
        }
        zero_acc();
        run_seg(ckA, 8);
        gbar();
        run_seg(ckB, 8);
        epilogue(3, g_h2[p], g_h2[1 - p], (char*)&g_h2bf[1 - p][mt][nt >> 1][0][0], nullptr);
        gbar();
        {
            const int row = blockIdx.x * 8 + wid;
            const float* hr = g_h2[1 - p] + (size_t)row * HD;
            float ss = 0.f;
#pragma unroll
            for (int q = 0; q < HD / 32; q++)
                ss += __ldcg(&hr[lane + 32 * q]) * outW[lane + 32 * q];
#pragma unroll
            for (int o = 16; o > 0; o >>= 1)
                ss += __shfl_xor_sync(0xffffffffu, ss, o);
            if (lane == 0) {
                const float v = ss + outb[0];
                g_y[row] = v;
                out[(size_t)row * PLEN + s] = v;
            }
        }
        gbar();
        p ^= 1;
    }
}

// ---------------------------------------------------------------------------
extern "C" void kernel_launch(void* const* d_in, const int* in_sizes, int n_in,
                              void* d_out, int out_size)
{
    const float* x      = (const float*)d_in[0];
    const float* eWih0  = (const float*)d_in[1];
    const float* eWhh0  = (const float*)d_in[2];
    const float* ebih0  = (const float*)d_in[3];
    const float* ebhh0  = (const float*)d_in[4];
    const float* eWih1  = (const float*)d_in[5];
    const float* eWhh1  = (const float*)d_in[6];
    const float* ebih1  = (const float*)d_in[7];
    const float* ebhh1  = (const float*)d_in[8];
    const float* dWih0  = (const float*)d_in[9];
    const float* dWhh0  = (const float*)d_in[10];
    const float* dbih0  = (const float*)d_in[11];
    const float* dbhh0  = (const float*)d_in[12];
    const float* dWih1  = (const float*)d_in[13];
    const float* dWhh1  = (const float*)d_in[14];
    const float* dbih1  = (const float*)d_in[15];
    const float* dbhh1  = (const float*)d_in[16];
    const float* outW   = (const float*)d_in[17];
    const float* outb   = (const float*)d_in[18];
    const float* dstart = (const float*)d_in[19];
    float* out = (float*)d_out;

    cudaFuncSetAttribute(gru_tc, cudaFuncAttributeMaxDynamicSharedMemorySize, SM_TOTAL);

    init_weights<<<1024, 256>>>(eWih0,
                                eWhh0, eWih1, eWhh1, dWhh0, dWih1, dWhh1,
                                ebih0, ebhh0, ebih1, ebhh1,
                                dbih0, dbhh0, dbih1, dbhh1);
    init_x<<<2048, 256>>>(x);
    gru_tc<<<NCTA, 256, SM_TOTAL>>>(dWih0, outW, outb, dstart, out);
}